// round 1
// baseline (speedup 1.0000x reference)
#include <cuda_runtime.h>
#include <cuda_bf16.h>
#include <math.h>

// Problem constants
#define B_   4
#define T_   2048
#define E_   1024
#define H_   16
#define S_   64
#define ROWS_ (B_ * T_)        // 8192
#define EPS_ 1e-5f

// ---------------- scratch (static device allocations only) ----------------
__device__ float g_q[ROWS_ * E_];
__device__ float g_k[ROWS_ * E_];
__device__ float g_v[ROWS_ * E_];
__device__ float g_o[ROWS_ * E_];

// ---------------------------------------------------------------------------
// GEMM: C[M,N] = A[M,K] @ B[N,K]^T   (A row-major MxK, B row-major NxK)
// Tiles: 128x128x8, 256 threads, 8x8 per-thread microtile.
// ---------------------------------------------------------------------------
__global__ __launch_bounds__(256) void gemm_nt(const float* __restrict__ A,
                                               const float* __restrict__ Bm,
                                               float* __restrict__ C,
                                               int M, int N, int K) {
    __shared__ float As[8][128];
    __shared__ float Bs[8][128];

    const int tid = threadIdx.x;
    const int m0 = blockIdx.y * 128;
    const int n0 = blockIdx.x * 128;

    const int lr = tid >> 1;           // 0..127 loader row
    const int lc = (tid & 1) * 4;      // 0 or 4 loader col (float4)
    const float* Ag = A + (size_t)(m0 + lr) * K + lc;
    const float* Bg = Bm + (size_t)(n0 + lr) * K + lc;

    const int tm = (tid >> 4) * 8;     // 0..120
    const int tn = (tid & 15) * 8;     // 0..120

    float acc[8][8];
#pragma unroll
    for (int i = 0; i < 8; i++)
#pragma unroll
        for (int j = 0; j < 8; j++) acc[i][j] = 0.f;

    for (int kk = 0; kk < K; kk += 8) {
        float4 a4 = *(const float4*)(Ag + kk);
        float4 b4 = *(const float4*)(Bg + kk);
        As[lc + 0][lr] = a4.x; As[lc + 1][lr] = a4.y;
        As[lc + 2][lr] = a4.z; As[lc + 3][lr] = a4.w;
        Bs[lc + 0][lr] = b4.x; Bs[lc + 1][lr] = b4.y;
        Bs[lc + 2][lr] = b4.z; Bs[lc + 3][lr] = b4.w;
        __syncthreads();

#pragma unroll
        for (int k = 0; k < 8; k++) {
            float4 aa0 = *(const float4*)&As[k][tm];
            float4 aa1 = *(const float4*)&As[k][tm + 4];
            float4 bb0 = *(const float4*)&Bs[k][tn];
            float4 bb1 = *(const float4*)&Bs[k][tn + 4];
            float a[8] = {aa0.x, aa0.y, aa0.z, aa0.w, aa1.x, aa1.y, aa1.z, aa1.w};
            float b[8] = {bb0.x, bb0.y, bb0.z, bb0.w, bb1.x, bb1.y, bb1.z, bb1.w};
#pragma unroll
            for (int i = 0; i < 8; i++)
#pragma unroll
                for (int j = 0; j < 8; j++) acc[i][j] = fmaf(a[i], b[j], acc[i][j]);
        }
        __syncthreads();
    }

#pragma unroll
    for (int i = 0; i < 8; i++) {
        float* cp = C + (size_t)(m0 + tm + i) * N + n0 + tn;
        float4 r0 = make_float4(acc[i][0], acc[i][1], acc[i][2], acc[i][3]);
        float4 r1 = make_float4(acc[i][4], acc[i][5], acc[i][6], acc[i][7]);
        *(float4*)(cp + 0) = r0;
        *(float4*)(cp + 4) = r1;
    }
}

// ---------------------------------------------------------------------------
// Per-head LayerNorm over last dim (64). In-place on y viewed as (rows, 64).
// One warp per row, 2 elements per lane.
// ---------------------------------------------------------------------------
__global__ __launch_bounds__(256) void ln_head(float* __restrict__ y,
                                               const float* __restrict__ w,
                                               const float* __restrict__ bia,
                                               int nrows) {
    const int warp = threadIdx.x >> 5;
    const int lane = threadIdx.x & 31;
    const int row = blockIdx.x * 8 + warp;
    if (row >= nrows) return;

    float* p = y + (size_t)row * 64 + lane * 2;
    float2 v = *(float2*)p;
    float s = v.x + v.y;
    float ss = v.x * v.x + v.y * v.y;
#pragma unroll
    for (int off = 16; off >= 1; off >>= 1) {
        s  += __shfl_xor_sync(0xffffffffu, s, off);
        ss += __shfl_xor_sync(0xffffffffu, ss, off);
    }
    const float mean = s * (1.f / 64.f);
    const float var  = ss * (1.f / 64.f) - mean * mean;
    const float rstd = rsqrtf(var + EPS_);

    float2 o;
    o.x = (v.x - mean) * rstd * w[lane * 2 + 0] + bia[lane * 2 + 0];
    o.y = (v.y - mean) * rstd * w[lane * 2 + 1] + bia[lane * 2 + 1];
    *(float2*)p = o;
}

// ---------------------------------------------------------------------------
// Flash-style causal attention. Layout (b, t, h, s): element (b,i,h,d) at
// (b*T+i)*E + h*64 + d.
// Grid: (T/64 q-tiles, B*H). Block: 256 threads.
// Q-tile 64 rows, KV-tile 32 rows, online softmax, O in registers.
// ---------------------------------------------------------------------------
__global__ __launch_bounds__(256) void attn_causal(const float* __restrict__ q,
                                                   const float* __restrict__ k,
                                                   const float* __restrict__ v,
                                                   float* __restrict__ o) {
    __shared__ float Qs[64][68];
    __shared__ float Ks[32][68];
    __shared__ float Vs[32][68];
    __shared__ float Ps[64][36];

    const int tid = threadIdx.x;
    const int bh = blockIdx.y;
    const int b  = bh >> 4;      // / H_
    const int h  = bh & 15;      // % H_
    const int i0 = blockIdx.x * 64;

    const size_t head_off = (size_t)b * T_ * E_ + (size_t)h * 64;
    const float* qb = q + head_off;
    const float* kb = k + head_off;
    const float* vb = v + head_off;

    // load Q tile: 64 rows x 64 floats, 4 threads per row, 16 floats each
    {
        const int r = tid >> 2;
        const int seg = (tid & 3) * 16;
        const float* src = qb + (size_t)(i0 + r) * E_ + seg;
#pragma unroll
        for (int f = 0; f < 4; f++) {
            float4 x4 = *(const float4*)(src + 4 * f);
            *(float4*)&Qs[r][seg + 4 * f] = x4;
        }
    }

    const int ty = tid >> 4;    // 0..15 -> rows ty*4..ty*4+3
    const int tx = tid & 15;    // 0..15

    float o_acc[4][4];
    float m_i[4], l_i[4];
#pragma unroll
    for (int ri = 0; ri < 4; ri++) {
        m_i[ri] = -1e30f; l_i[ri] = 0.f;
#pragma unroll
        for (int c = 0; c < 4; c++) o_acc[ri][c] = 0.f;
    }

    const float scale = 0.125f; // 1/sqrt(64)
    const int jend = i0 + 64;   // causal: j0 < jend

    for (int j0 = 0; j0 < jend; j0 += 32) {
        // load K,V tiles: 32 rows x 64 floats each; 8 threads per row, 8 floats each
        {
            const int r = tid >> 3;
            const int seg = (tid & 7) * 8;
            const float* ks = kb + (size_t)(j0 + r) * E_ + seg;
            const float* vs = vb + (size_t)(j0 + r) * E_ + seg;
            *(float4*)&Ks[r][seg + 0] = *(const float4*)(ks + 0);
            *(float4*)&Ks[r][seg + 4] = *(const float4*)(ks + 4);
            *(float4*)&Vs[r][seg + 0] = *(const float4*)(vs + 0);
            *(float4*)&Vs[r][seg + 4] = *(const float4*)(vs + 4);
        }
        __syncthreads();

        // S = Q Kt : thread owns rows ty*4+{0..3}, cols tx*2+{0,1}
        float s[4][2];
#pragma unroll
        for (int ri = 0; ri < 4; ri++) { s[ri][0] = 0.f; s[ri][1] = 0.f; }
#pragma unroll
        for (int d = 0; d < 64; d += 4) {
            float4 b0 = *(const float4*)&Ks[tx * 2 + 0][d];
            float4 b1 = *(const float4*)&Ks[tx * 2 + 1][d];
#pragma unroll
            for (int ri = 0; ri < 4; ri++) {
                float4 a = *(const float4*)&Qs[ty * 4 + ri][d];
                s[ri][0] += a.x * b0.x + a.y * b0.y + a.z * b0.z + a.w * b0.w;
                s[ri][1] += a.x * b1.x + a.y * b1.y + a.z * b1.z + a.w * b1.w;
            }
        }

        // scale + causal mask + online softmax update
#pragma unroll
        for (int ri = 0; ri < 4; ri++) {
            const int gi = i0 + ty * 4 + ri;
            const int gj0 = j0 + tx * 2;
            float s0 = (gj0 + 0 <= gi) ? s[ri][0] * scale : -1e30f;
            float s1 = (gj0 + 1 <= gi) ? s[ri][1] * scale : -1e30f;

            float mt = fmaxf(s0, s1);
#pragma unroll
            for (int off = 8; off >= 1; off >>= 1)
                mt = fmaxf(mt, __shfl_xor_sync(0xffffffffu, mt, off));

            const float mnew = fmaxf(m_i[ri], mt);
            const float corr = __expf(m_i[ri] - mnew);
            const float p0 = __expf(s0 - mnew);
            const float p1 = __expf(s1 - mnew);
            float rs = p0 + p1;
#pragma unroll
            for (int off = 8; off >= 1; off >>= 1)
                rs += __shfl_xor_sync(0xffffffffu, rs, off);

            l_i[ri] = l_i[ri] * corr + rs;
            m_i[ri] = mnew;
#pragma unroll
            for (int c = 0; c < 4; c++) o_acc[ri][c] *= corr;

            Ps[ty * 4 + ri][tx * 2 + 0] = p0;
            Ps[ty * 4 + ri][tx * 2 + 1] = p1;
        }
        __syncthreads();

        // O += P @ V : thread owns rows ty*4+{0..3}, dims tx*4+{0..3}
#pragma unroll
        for (int j = 0; j < 32; j++) {
            float4 vv = *(const float4*)&Vs[j][tx * 4];
#pragma unroll
            for (int ri = 0; ri < 4; ri++) {
                const float pp = Ps[ty * 4 + ri][j];
                o_acc[ri][0] = fmaf(pp, vv.x, o_acc[ri][0]);
                o_acc[ri][1] = fmaf(pp, vv.y, o_acc[ri][1]);
                o_acc[ri][2] = fmaf(pp, vv.z, o_acc[ri][2]);
                o_acc[ri][3] = fmaf(pp, vv.w, o_acc[ri][3]);
            }
        }
        __syncthreads(); // before next tile's smem overwrite
    }

    // epilogue: divide by l, store to (b, i, h, d)
#pragma unroll
    for (int ri = 0; ri < 4; ri++) {
        const float inv = 1.f / l_i[ri];
        float4 r = make_float4(o_acc[ri][0] * inv, o_acc[ri][1] * inv,
                               o_acc[ri][2] * inv, o_acc[ri][3] * inv);
        float* dst = o + (size_t)(b * T_ + i0 + ty * 4 + ri) * E_ + h * 64 + tx * 4;
        *(float4*)dst = r;
    }
}

// ---------------------------------------------------------------------------
// Launch
// ---------------------------------------------------------------------------
extern "C" void kernel_launch(void* const* d_in, const int* in_sizes, int n_in,
                              void* d_out, int out_size) {
    const float* x     = (const float*)d_in[0];
    const float* Wk    = (const float*)d_in[1];
    const float* Wq    = (const float*)d_in[2];
    const float* Wv    = (const float*)d_in[3];
    const float* Wu    = (const float*)d_in[4];
    const float* kln_w = (const float*)d_in[5];
    const float* kln_b = (const float*)d_in[6];
    const float* qln_w = (const float*)d_in[7];
    const float* qln_b = (const float*)d_in[8];
    float* out = (float*)d_out;

    float *qp, *kp, *vp, *op;
    cudaGetSymbolAddress((void**)&qp, g_q);
    cudaGetSymbolAddress((void**)&kp, g_k);
    cudaGetSymbolAddress((void**)&vp, g_v);
    cudaGetSymbolAddress((void**)&op, g_o);

    dim3 gGemm(E_ / 128, ROWS_ / 128);  // (8, 64)
    gemm_nt<<<gGemm, 256>>>(x, Wk, kp, ROWS_, E_, E_);
    gemm_nt<<<gGemm, 256>>>(x, Wq, qp, ROWS_, E_, E_);
    gemm_nt<<<gGemm, 256>>>(x, Wv, vp, ROWS_, E_, E_);

    const int ln_rows = ROWS_ * H_;           // 131072 rows of 64
    ln_head<<<ln_rows / 8, 256>>>(kp, kln_w, kln_b, ln_rows);
    ln_head<<<ln_rows / 8, 256>>>(qp, qln_w, qln_b, ln_rows);

    dim3 gAttn(T_ / 64, B_ * H_);             // (32, 64)
    attn_causal<<<gAttn, 256>>>(qp, kp, vp, op);

    gemm_nt<<<gGemm, 256>>>(op, Wu, out, ROWS_, E_, E_);
}

// round 3
// speedup vs baseline: 1.1830x; 1.1830x over previous
#include <cuda_runtime.h>
#include <cuda_bf16.h>
#include <math.h>
#include <stdint.h>

// Problem constants
#define B_   4
#define T_   2048
#define E_   1024
#define H_   16
#define S_   64
#define ROWS_ (B_ * T_)        // 8192
#define EPS_ 1e-5f

// ---------------- scratch (static device allocations only) ----------------
__device__ float g_q[ROWS_ * E_];
__device__ float g_k[ROWS_ * E_];
__device__ float g_v[ROWS_ * E_];
__device__ float g_o[ROWS_ * E_];

// ============================================================================
// PTX helpers (legacy sm_80-era instructions only — the harness emits
// compute_103 (non-'a') virtual PTX, so sm_103a-only features are unavailable)
// ============================================================================
__device__ __forceinline__ uint32_t smem_u32(const void* p) {
    uint32_t a;
    asm("{ .reg .u64 t; cvta.to.shared.u64 t, %1; cvt.u32.u64 %0, t; }"
        : "=r"(a) : "l"(p));
    return a;
}

__device__ __forceinline__ void cp16(uint32_t dst, const void* src) {
    asm volatile("cp.async.cg.shared.global [%0], [%1], 16;"
                 :: "r"(dst), "l"(src) : "memory");
}
#define CP_COMMIT() asm volatile("cp.async.commit_group;" ::: "memory")
#define CP_WAIT(n)  asm volatile("cp.async.wait_group %0;" :: "n"(n) : "memory")

#define LDSM_X4(r0, r1, r2, r3, addr) \
    asm volatile("ldmatrix.sync.aligned.m8n8.x4.shared.b16 {%0,%1,%2,%3}, [%4];" \
                 : "=r"(r0), "=r"(r1), "=r"(r2), "=r"(r3) : "r"(addr))

__device__ __forceinline__ void split_tf32(uint32_t raw, uint32_t& hi, uint32_t& lo) {
    float x = __uint_as_float(raw);
    asm("cvt.rna.tf32.f32 %0, %1;" : "=r"(hi) : "f"(x));
    float l = x - __uint_as_float(hi);
    asm("cvt.rna.tf32.f32 %0, %1;" : "=r"(lo) : "f"(l));
}

__device__ __forceinline__ void mma_tf32(float* d, const uint32_t* a,
                                         uint32_t b0, uint32_t b1) {
    asm volatile(
        "mma.sync.aligned.m16n8k8.row.col.f32.tf32.tf32.f32 "
        "{%0,%1,%2,%3}, {%4,%5,%6,%7}, {%8,%9}, {%0,%1,%2,%3};"
        : "+f"(d[0]), "+f"(d[1]), "+f"(d[2]), "+f"(d[3])
        : "r"(a[0]), "r"(a[1]), "r"(a[2]), "r"(a[3]), "r"(b0), "r"(b1));
}

// ============================================================================
// 3xTF32 split GEMM: C[8192,1024] = A[8192,1024] @ B[1024,1024]^T (fp32 io).
// CTA tile 128x128, K-stage 32, 4-stage cp.async pipeline, 8 warps (64x32 each).
// Grid: (8, 64), 256 threads. Dynamic smem: 4 * 32KB.
// ============================================================================
#define GN 1024
#define GK 1024
#define NSTAGE 4
#define STAGE_BYTES 32768
#define SMEM_GEMM_TOTAL (NSTAGE * STAGE_BYTES)   // 131072

__global__ __launch_bounds__(256) void gemm_tf32_split(
    const float* __restrict__ A, const float* __restrict__ Bm,
    float* __restrict__ C) {
    extern __shared__ __align__(1024) char smem[];
    const uint32_t smem_base = smem_u32(smem);

    const int tid = threadIdx.x;
    const int lane = tid & 31;
    const int wid = tid >> 5;
    const int m0 = blockIdx.y * 128;
    const int n0 = blockIdx.x * 128;
    const int wm = (wid >> 2) * 64;   // 0 or 64
    const int wn = (wid & 3) * 32;    // 0,32,64,96

    // ---- cp.async loader mapping: 2 threads per row, 64B each ----
    const int row2 = tid >> 1;        // 0..127
    const int half = tid & 1;
    const uint32_t mask2 = (row2 & 7) << 4;
    const float* Ag = A + (size_t)(m0 + row2) * GK + half * 16;
    const float* Bg = Bm + (size_t)(n0 + row2) * GK + half * 16;

    // ---- ldmatrix per-lane address components ----
    // A frag (16x8): mats at rows {0-7, 8-15} x kcols {0-3, 4-7}
    const int a_lrow = (lane & 7) + ((lane >> 3) & 1) * 8;   // 0..15
    const uint32_t a_lkx = ((lane >> 4) & 1) * 16;           // byte offset 0/16
    uint32_t arbase[4], amask[4];
#pragma unroll
    for (int mf = 0; mf < 4; mf++) {
        const int r = wm + mf * 16 + a_lrow;
        arbase[mf] = (uint32_t)r * 128;
        amask[mf] = (r & 7) << 4;
    }
    // B x4 covers two n8 frags: mats rows {0-7, 8-15} paired as (b0,b1) per frag
    const int b_lrow = (lane & 7) + ((lane >> 4) & 1) * 8;
    const uint32_t b_lkx = ((lane >> 3) & 1) * 16;
    uint32_t brbase[2], bmask[2];
#pragma unroll
    for (int np = 0; np < 2; np++) {
        const int r = wn + np * 16 + b_lrow;
        brbase[np] = (uint32_t)r * 128;
        bmask[np] = (r & 7) << 4;
    }

    float acc[4][4][4];
#pragma unroll
    for (int i = 0; i < 4; i++)
#pragma unroll
        for (int j = 0; j < 4; j++)
#pragma unroll
            for (int r = 0; r < 4; r++) acc[i][j][r] = 0.f;

    auto issue_load = [&](int c, int s) {
        const uint32_t stA = smem_base + s * STAGE_BYTES;
        const uint32_t stB = stA + 16384;
        const float* ga = Ag + c * 32;
        const float* gb = Bg + c * 32;
#pragma unroll
        for (int v = 0; v < 4; v++) {
            const uint32_t koff = half * 64 + v * 16;
            const uint32_t d = row2 * 128 + (koff ^ mask2);
            cp16(stA + d, ga + v * 4);
            cp16(stB + d, gb + v * 4);
        }
    };

    // prologue: prefetch 3 stages
    issue_load(0, 0); CP_COMMIT();
    issue_load(1, 1); CP_COMMIT();
    issue_load(2, 2); CP_COMMIT();

    const int NCHUNK = GK / 32;   // 32
    for (int c = 0; c < NCHUNK; c++) {
        CP_WAIT(2);
        __syncthreads();
        if (c + 3 < NCHUNK) issue_load(c + 3, (c + 3) & 3);
        CP_COMMIT();   // empty group in the tail keeps wait accounting uniform

        const uint32_t stA = smem_base + (c & 3) * STAGE_BYTES;
        const uint32_t stB = stA + 16384;

#pragma unroll
        for (int ks = 0; ks < 4; ks++) {
            const uint32_t koffA = ks * 32 + a_lkx;
            const uint32_t koffB = ks * 32 + b_lkx;

            uint32_t ahi[4][4], alo[4][4];
#pragma unroll
            for (int mf = 0; mf < 4; mf++) {
                uint32_t r0, r1, r2, r3;
                LDSM_X4(r0, r1, r2, r3, stA + arbase[mf] + (koffA ^ amask[mf]));
                split_tf32(r0, ahi[mf][0], alo[mf][0]);
                split_tf32(r1, ahi[mf][1], alo[mf][1]);
                split_tf32(r2, ahi[mf][2], alo[mf][2]);
                split_tf32(r3, ahi[mf][3], alo[mf][3]);
            }
            uint32_t bhi[8], blo[8];
#pragma unroll
            for (int np = 0; np < 2; np++) {
                uint32_t r0, r1, r2, r3;
                LDSM_X4(r0, r1, r2, r3, stB + brbase[np] + (koffB ^ bmask[np]));
                split_tf32(r0, bhi[np * 4 + 0], blo[np * 4 + 0]);
                split_tf32(r1, bhi[np * 4 + 1], blo[np * 4 + 1]);
                split_tf32(r2, bhi[np * 4 + 2], blo[np * 4 + 2]);
                split_tf32(r3, bhi[np * 4 + 3], blo[np * 4 + 3]);
            }

#pragma unroll
            for (int mf = 0; mf < 4; mf++) {
#pragma unroll
                for (int nf = 0; nf < 4; nf++) {
                    const int ix = (nf >> 1) * 4 + (nf & 1) * 2;
                    mma_tf32(acc[mf][nf], ahi[mf], bhi[ix], bhi[ix + 1]);
                    mma_tf32(acc[mf][nf], ahi[mf], blo[ix], blo[ix + 1]);
                    mma_tf32(acc[mf][nf], alo[mf], bhi[ix], bhi[ix + 1]);
                }
            }
        }
    }

    // epilogue: fragment -> global
    const int groupID = lane >> 2;
    const int tig = lane & 3;
#pragma unroll
    for (int mf = 0; mf < 4; mf++) {
        const size_t r = (size_t)(m0 + wm + mf * 16 + groupID);
#pragma unroll
        for (int nf = 0; nf < 4; nf++) {
            const int cidx = n0 + wn + nf * 8 + tig * 2;
            float2 v01 = make_float2(acc[mf][nf][0], acc[mf][nf][1]);
            float2 v23 = make_float2(acc[mf][nf][2], acc[mf][nf][3]);
            *(float2*)(C + r * GN + cidx) = v01;
            *(float2*)(C + (r + 8) * GN + cidx) = v23;
        }
    }
}

// ---------------------------------------------------------------------------
// Per-head LayerNorm over last dim (64). In-place on y viewed as (rows, 64).
// ---------------------------------------------------------------------------
__global__ __launch_bounds__(256) void ln_head(float* __restrict__ y,
                                               const float* __restrict__ w,
                                               const float* __restrict__ bia,
                                               int nrows) {
    const int warp = threadIdx.x >> 5;
    const int lane = threadIdx.x & 31;
    const int row = blockIdx.x * 8 + warp;
    if (row >= nrows) return;

    float* p = y + (size_t)row * 64 + lane * 2;
    float2 v = *(float2*)p;
    float s = v.x + v.y;
    float ss = v.x * v.x + v.y * v.y;
#pragma unroll
    for (int off = 16; off >= 1; off >>= 1) {
        s  += __shfl_xor_sync(0xffffffffu, s, off);
        ss += __shfl_xor_sync(0xffffffffu, ss, off);
    }
    const float mean = s * (1.f / 64.f);
    const float var  = ss * (1.f / 64.f) - mean * mean;
    const float rstd = rsqrtf(var + EPS_);

    float2 o;
    o.x = (v.x - mean) * rstd * w[lane * 2 + 0] + bia[lane * 2 + 0];
    o.y = (v.y - mean) * rstd * w[lane * 2 + 1] + bia[lane * 2 + 1];
    *(float2*)p = o;
}

// ---------------------------------------------------------------------------
// Flash-style causal attention (unchanged from R1).
// ---------------------------------------------------------------------------
__global__ __launch_bounds__(256) void attn_causal(const float* __restrict__ q,
                                                   const float* __restrict__ k,
                                                   const float* __restrict__ v,
                                                   float* __restrict__ o) {
    __shared__ float Qs[64][68];
    __shared__ float Ks[32][68];
    __shared__ float Vs[32][68];
    __shared__ float Ps[64][36];

    const int tid = threadIdx.x;
    const int bh = blockIdx.y;
    const int b  = bh >> 4;
    const int h  = bh & 15;
    const int i0 = blockIdx.x * 64;

    const size_t head_off = (size_t)b * T_ * E_ + (size_t)h * 64;
    const float* qb = q + head_off;
    const float* kb = k + head_off;
    const float* vb = v + head_off;

    {
        const int r = tid >> 2;
        const int seg = (tid & 3) * 16;
        const float* src = qb + (size_t)(i0 + r) * E_ + seg;
#pragma unroll
        for (int f = 0; f < 4; f++) {
            float4 x4 = *(const float4*)(src + 4 * f);
            *(float4*)&Qs[r][seg + 4 * f] = x4;
        }
    }

    const int ty = tid >> 4;
    const int tx = tid & 15;

    float o_acc[4][4];
    float m_i[4], l_i[4];
#pragma unroll
    for (int ri = 0; ri < 4; ri++) {
        m_i[ri] = -1e30f; l_i[ri] = 0.f;
#pragma unroll
        for (int c = 0; c < 4; c++) o_acc[ri][c] = 0.f;
    }

    const float scale = 0.125f;
    const int jend = i0 + 64;

    for (int j0 = 0; j0 < jend; j0 += 32) {
        {
            const int r = tid >> 3;
            const int seg = (tid & 7) * 8;
            const float* ks = kb + (size_t)(j0 + r) * E_ + seg;
            const float* vs = vb + (size_t)(j0 + r) * E_ + seg;
            *(float4*)&Ks[r][seg + 0] = *(const float4*)(ks + 0);
            *(float4*)&Ks[r][seg + 4] = *(const float4*)(ks + 4);
            *(float4*)&Vs[r][seg + 0] = *(const float4*)(vs + 0);
            *(float4*)&Vs[r][seg + 4] = *(const float4*)(vs + 4);
        }
        __syncthreads();

        float s[4][2];
#pragma unroll
        for (int ri = 0; ri < 4; ri++) { s[ri][0] = 0.f; s[ri][1] = 0.f; }
#pragma unroll
        for (int d = 0; d < 64; d += 4) {
            float4 b0 = *(const float4*)&Ks[tx * 2 + 0][d];
            float4 b1 = *(const float4*)&Ks[tx * 2 + 1][d];
#pragma unroll
            for (int ri = 0; ri < 4; ri++) {
                float4 a = *(const float4*)&Qs[ty * 4 + ri][d];
                s[ri][0] += a.x * b0.x + a.y * b0.y + a.z * b0.z + a.w * b0.w;
                s[ri][1] += a.x * b1.x + a.y * b1.y + a.z * b1.z + a.w * b1.w;
            }
        }

#pragma unroll
        for (int ri = 0; ri < 4; ri++) {
            const int gi = i0 + ty * 4 + ri;
            const int gj0 = j0 + tx * 2;
            float s0 = (gj0 + 0 <= gi) ? s[ri][0] * scale : -1e30f;
            float s1 = (gj0 + 1 <= gi) ? s[ri][1] * scale : -1e30f;

            float mt = fmaxf(s0, s1);
#pragma unroll
            for (int off = 8; off >= 1; off >>= 1)
                mt = fmaxf(mt, __shfl_xor_sync(0xffffffffu, mt, off));

            const float mnew = fmaxf(m_i[ri], mt);
            const float corr = __expf(m_i[ri] - mnew);
            const float p0 = __expf(s0 - mnew);
            const float p1 = __expf(s1 - mnew);
            float rs = p0 + p1;
#pragma unroll
            for (int off = 8; off >= 1; off >>= 1)
                rs += __shfl_xor_sync(0xffffffffu, rs, off);

            l_i[ri] = l_i[ri] * corr + rs;
            m_i[ri] = mnew;
#pragma unroll
            for (int c = 0; c < 4; c++) o_acc[ri][c] *= corr;

            Ps[ty * 4 + ri][tx * 2 + 0] = p0;
            Ps[ty * 4 + ri][tx * 2 + 1] = p1;
        }
        __syncthreads();

#pragma unroll
        for (int j = 0; j < 32; j++) {
            float4 vv = *(const float4*)&Vs[j][tx * 4];
#pragma unroll
            for (int ri = 0; ri < 4; ri++) {
                const float pp = Ps[ty * 4 + ri][j];
                o_acc[ri][0] = fmaf(pp, vv.x, o_acc[ri][0]);
                o_acc[ri][1] = fmaf(pp, vv.y, o_acc[ri][1]);
                o_acc[ri][2] = fmaf(pp, vv.z, o_acc[ri][2]);
                o_acc[ri][3] = fmaf(pp, vv.w, o_acc[ri][3]);
            }
        }
        __syncthreads();
    }

#pragma unroll
    for (int ri = 0; ri < 4; ri++) {
        const float inv = 1.f / l_i[ri];
        float4 r = make_float4(o_acc[ri][0] * inv, o_acc[ri][1] * inv,
                               o_acc[ri][2] * inv, o_acc[ri][3] * inv);
        float* dst = o + (size_t)(b * T_ + i0 + ty * 4 + ri) * E_ + h * 64 + tx * 4;
        *(float4*)dst = r;
    }
}

// ---------------------------------------------------------------------------
// Launch
// ---------------------------------------------------------------------------
extern "C" void kernel_launch(void* const* d_in, const int* in_sizes, int n_in,
                              void* d_out, int out_size) {
    const float* x     = (const float*)d_in[0];
    const float* Wk    = (const float*)d_in[1];
    const float* Wq    = (const float*)d_in[2];
    const float* Wv    = (const float*)d_in[3];
    const float* Wu    = (const float*)d_in[4];
    const float* kln_w = (const float*)d_in[5];
    const float* kln_b = (const float*)d_in[6];
    const float* qln_w = (const float*)d_in[7];
    const float* qln_b = (const float*)d_in[8];
    float* out = (float*)d_out;

    float *qp, *kp, *vp, *op;
    cudaGetSymbolAddress((void**)&qp, g_q);
    cudaGetSymbolAddress((void**)&kp, g_k);
    cudaGetSymbolAddress((void**)&vp, g_v);
    cudaGetSymbolAddress((void**)&op, g_o);

    cudaFuncSetAttribute(gemm_tf32_split,
                         cudaFuncAttributeMaxDynamicSharedMemorySize,
                         SMEM_GEMM_TOTAL);

    dim3 gGemm(E_ / 128, ROWS_ / 128);  // (8, 64)
    gemm_tf32_split<<<gGemm, 256, SMEM_GEMM_TOTAL>>>(x, Wk, kp);
    gemm_tf32_split<<<gGemm, 256, SMEM_GEMM_TOTAL>>>(x, Wq, qp);
    gemm_tf32_split<<<gGemm, 256, SMEM_GEMM_TOTAL>>>(x, Wv, vp);

    const int ln_rows = ROWS_ * H_;
    ln_head<<<ln_rows / 8, 256>>>(kp, kln_w, kln_b, ln_rows);
    ln_head<<<ln_rows / 8, 256>>>(qp, qln_w, qln_b, ln_rows);

    dim3 gAttn(T_ / 64, B_ * H_);
    attn_causal<<<gAttn, 256>>>(qp, kp, vp, op);

    gemm_tf32_split<<<gGemm, 256, SMEM_GEMM_TOTAL>>>(op, Wu, out);
}

// round 4
// speedup vs baseline: 1.5708x; 1.3278x over previous
#include <cuda_runtime.h>
#include <cuda_bf16.h>
#include <math.h>
#include <stdint.h>

// Problem constants
#define B_   4
#define T_   2048
#define E_   1024
#define H_   16
#define S_   64
#define ROWS_ (B_ * T_)        // 8192
#define EPS_ 1e-5f

// ---------------- scratch (static device allocations only) ----------------
__device__ float g_q[ROWS_ * E_];
__device__ float g_k[ROWS_ * E_];
__device__ float g_v[ROWS_ * E_];
__device__ __nv_bfloat16 g_xh[ROWS_ * E_];
__device__ __nv_bfloat16 g_xl[ROWS_ * E_];
__device__ __nv_bfloat16 g_oh[ROWS_ * E_];
__device__ __nv_bfloat16 g_ol[ROWS_ * E_];
__device__ __nv_bfloat16 g_wh[4][E_ * E_];   // Wk, Wq, Wv, Wu (hi)
__device__ __nv_bfloat16 g_wl[4][E_ * E_];   // (lo)

// ============================================================================
// PTX helpers (sm_80-era only; harness emits compute_103 non-'a' PTX)
// ============================================================================
__device__ __forceinline__ uint32_t smem_u32(const void* p) {
    uint32_t a;
    asm("{ .reg .u64 t; cvta.to.shared.u64 t, %1; cvt.u32.u64 %0, t; }"
        : "=r"(a) : "l"(p));
    return a;
}
__device__ __forceinline__ void cp16(uint32_t dst, const void* src) {
    asm volatile("cp.async.cg.shared.global [%0], [%1], 16;"
                 :: "r"(dst), "l"(src) : "memory");
}
#define CP_COMMIT() asm volatile("cp.async.commit_group;" ::: "memory")
#define CP_WAIT(n)  asm volatile("cp.async.wait_group %0;" :: "n"(n) : "memory")

#define LDSM_X4(r0, r1, r2, r3, addr) \
    asm volatile("ldmatrix.sync.aligned.m8n8.x4.shared.b16 {%0,%1,%2,%3}, [%4];" \
                 : "=r"(r0), "=r"(r1), "=r"(r2), "=r"(r3) : "r"(addr))

__device__ __forceinline__ void mma_bf16(float* d, const uint32_t* a,
                                         uint32_t b0, uint32_t b1) {
    asm volatile(
        "mma.sync.aligned.m16n8k16.row.col.f32.bf16.bf16.f32 "
        "{%0,%1,%2,%3}, {%4,%5,%6,%7}, {%8,%9}, {%0,%1,%2,%3};"
        : "+f"(d[0]), "+f"(d[1]), "+f"(d[2]), "+f"(d[3])
        : "r"(a[0]), "r"(a[1]), "r"(a[2]), "r"(a[3]), "r"(b0), "r"(b1));
}

// ============================================================================
// fp32 -> (bf16 hi, bf16 lo) split.  x ~= hi + lo; lo = bf16(x - float(hi)).
// ============================================================================
__global__ __launch_bounds__(256) void split_bf16(const float* __restrict__ in,
                                                  __nv_bfloat16* __restrict__ hi,
                                                  __nv_bfloat16* __restrict__ lo,
                                                  int n4) {
    int i = blockIdx.x * blockDim.x + threadIdx.x;
    if (i >= n4) return;
    float4 x = ((const float4*)in)[i];
    __nv_bfloat16 h[4], l[4];
    float xs[4] = {x.x, x.y, x.z, x.w};
#pragma unroll
    for (int j = 0; j < 4; j++) {
        h[j] = __float2bfloat16(xs[j]);
        l[j] = __float2bfloat16(xs[j] - __bfloat162float(h[j]));
    }
    ((uint2*)hi)[i] = *(uint2*)h;
    ((uint2*)lo)[i] = *(uint2*)l;
}

// ============================================================================
// 3-term bf16-split GEMM: C[8192,1024] = A @ B^T (logical fp32).
// A given as (Ah, Al) bf16 [8192,1024]; B as (Bh, Bl) bf16 [1024,1024].
// CTA tile 128x128, K-chunk 64, 3-stage cp.async, 8 warps (64x32 warp tile).
// gridDim.z selects among up to 3 (B, C) pairs (QKV fusion).
// ============================================================================
#define GN 1024
#define GK 1024
#define KCH 64
#define NCHUNK (GK / KCH)       // 16
#define TILE_BYTES 16384        // 128 x 64 bf16
#define STAGE_BYTES (4 * TILE_BYTES)   // Ahi, Alo, Bhi, Blo
#define SMEM_GEMM_TOTAL (3 * STAGE_BYTES)   // 196608

__global__ __launch_bounds__(256) void gemm_bf16_split(
    const __nv_bfloat16* __restrict__ Ah, const __nv_bfloat16* __restrict__ Al,
    const __nv_bfloat16* Bh0, const __nv_bfloat16* Bl0, float* C0,
    const __nv_bfloat16* Bh1, const __nv_bfloat16* Bl1, float* C1,
    const __nv_bfloat16* Bh2, const __nv_bfloat16* Bl2, float* C2) {
    extern __shared__ __align__(1024) char smem[];
    const uint32_t smem_base = smem_u32(smem);

    const __nv_bfloat16* Bh = (blockIdx.z == 0) ? Bh0 : (blockIdx.z == 1) ? Bh1 : Bh2;
    const __nv_bfloat16* Bl = (blockIdx.z == 0) ? Bl0 : (blockIdx.z == 1) ? Bl1 : Bl2;
    float* C = (blockIdx.z == 0) ? C0 : (blockIdx.z == 1) ? C1 : C2;

    const int tid = threadIdx.x;
    const int lane = tid & 31;
    const int wid = tid >> 5;
    const int m0 = blockIdx.y * 128;
    const int n0 = blockIdx.x * 128;
    const int wm = (wid >> 2) * 64;
    const int wn = (wid & 3) * 32;

    // loader: 2 threads/row, 4x16B chunks each per tile
    const int row2 = tid >> 1;       // 0..127
    const int half = tid & 1;
    const uint32_t lmask = (row2 & 7) << 4;
    const __nv_bfloat16* gAh = Ah + (size_t)(m0 + row2) * GK;
    const __nv_bfloat16* gAl = Al + (size_t)(m0 + row2) * GK;
    const __nv_bfloat16* gBh = Bh + (size_t)(n0 + row2) * GK;
    const __nv_bfloat16* gBl = Bl + (size_t)(n0 + row2) * GK;

    // ldmatrix lane addressing (128B rows, sw128)
    const int a_lrow = (lane & 7) + ((lane >> 3) & 1) * 8;
    const uint32_t a_lkx = ((lane >> 4) & 1) * 16;
    uint32_t arbase[4], amask[4];
#pragma unroll
    for (int mf = 0; mf < 4; mf++) {
        const int r = wm + mf * 16 + a_lrow;
        arbase[mf] = (uint32_t)r * 128;
        amask[mf] = (r & 7) << 4;
    }
    const int b_lrow = (lane & 7) + ((lane >> 4) & 1) * 8;
    const uint32_t b_lkx = ((lane >> 3) & 1) * 16;
    uint32_t brbase[2], bmask[2];
#pragma unroll
    for (int np = 0; np < 2; np++) {
        const int r = wn + np * 16 + b_lrow;
        brbase[np] = (uint32_t)r * 128;
        bmask[np] = (r & 7) << 4;
    }

    float acc[4][4][4];
#pragma unroll
    for (int i = 0; i < 4; i++)
#pragma unroll
        for (int j = 0; j < 4; j++)
#pragma unroll
            for (int r = 0; r < 4; r++) acc[i][j][r] = 0.f;

    auto issue_load = [&](int c, int s) {
        const uint32_t st = smem_base + s * STAGE_BYTES;
        const int ke = c * KCH;    // element offset
#pragma unroll
        for (int v = 0; v < 4; v++) {
            const uint32_t koff = half * 64 + v * 16;        // bytes in row
            const uint32_t d = row2 * 128 + (koff ^ lmask);
            const int kel = ke + (int)(koff >> 1);           // elements
            cp16(st + d,                  gAh + kel);
            cp16(st + TILE_BYTES + d,     gAl + kel);
            cp16(st + 2 * TILE_BYTES + d, gBh + kel);
            cp16(st + 3 * TILE_BYTES + d, gBl + kel);
        }
    };

    issue_load(0, 0); CP_COMMIT();
    issue_load(1, 1); CP_COMMIT();

    for (int c = 0; c < NCHUNK; c++) {
        CP_WAIT(1);
        __syncthreads();
        if (c + 2 < NCHUNK) issue_load(c + 2, (c + 2) % 3);
        CP_COMMIT();

        const uint32_t st = smem_base + (c % 3) * STAGE_BYTES;
        const uint32_t stAh = st;
        const uint32_t stAl = st + TILE_BYTES;
        const uint32_t stBh = st + 2 * TILE_BYTES;
        const uint32_t stBl = st + 3 * TILE_BYTES;

#pragma unroll
        for (int ks = 0; ks < 4; ks++) {
            const uint32_t koffA = ks * 32 + a_lkx;
            const uint32_t koffB = ks * 32 + b_lkx;

            uint32_t ah[4][4], al[4][4];
#pragma unroll
            for (int mf = 0; mf < 4; mf++) {
                const uint32_t off = arbase[mf] + (koffA ^ amask[mf]);
                LDSM_X4(ah[mf][0], ah[mf][1], ah[mf][2], ah[mf][3], stAh + off);
                LDSM_X4(al[mf][0], al[mf][1], al[mf][2], al[mf][3], stAl + off);
            }
            uint32_t bh[8], bl[8];
#pragma unroll
            for (int np = 0; np < 2; np++) {
                const uint32_t off = brbase[np] + (koffB ^ bmask[np]);
                LDSM_X4(bh[np * 4 + 0], bh[np * 4 + 1], bh[np * 4 + 2], bh[np * 4 + 3],
                        stBh + off);
                LDSM_X4(bl[np * 4 + 0], bl[np * 4 + 1], bl[np * 4 + 2], bl[np * 4 + 3],
                        stBl + off);
            }

#pragma unroll
            for (int mf = 0; mf < 4; mf++) {
#pragma unroll
                for (int nf = 0; nf < 4; nf++) {
                    // frag nf: regs {ix, ix+1} where matrices are
                    // [n0-7 kLo, n0-7 kHi, n8-15 kLo, n8-15 kHi] per ldsm.x4
                    const int ix = (nf >> 1) * 4 + (nf & 1) * 2;
                    mma_bf16(acc[mf][nf], ah[mf], bh[ix], bh[ix + 1]);
                    mma_bf16(acc[mf][nf], ah[mf], bl[ix], bl[ix + 1]);
                    mma_bf16(acc[mf][nf], al[mf], bh[ix], bh[ix + 1]);
                }
            }
        }
    }

    const int groupID = lane >> 2;
    const int tig = lane & 3;
#pragma unroll
    for (int mf = 0; mf < 4; mf++) {
        const size_t r = (size_t)(m0 + wm + mf * 16 + groupID);
#pragma unroll
        for (int nf = 0; nf < 4; nf++) {
            const int cidx = n0 + wn + nf * 8 + tig * 2;
            *(float2*)(C + r * GN + cidx) = make_float2(acc[mf][nf][0], acc[mf][nf][1]);
            *(float2*)(C + (r + 8) * GN + cidx) = make_float2(acc[mf][nf][2], acc[mf][nf][3]);
        }
    }
}

// ---------------------------------------------------------------------------
// Per-head LayerNorm over last dim (64). In-place.
// ---------------------------------------------------------------------------
__global__ __launch_bounds__(256) void ln_head(float* __restrict__ y,
                                               const float* __restrict__ w,
                                               const float* __restrict__ bia,
                                               int nrows) {
    const int warp = threadIdx.x >> 5;
    const int lane = threadIdx.x & 31;
    const int row = blockIdx.x * 8 + warp;
    if (row >= nrows) return;

    float* p = y + (size_t)row * 64 + lane * 2;
    float2 v = *(float2*)p;
    float s = v.x + v.y;
    float ss = v.x * v.x + v.y * v.y;
#pragma unroll
    for (int off = 16; off >= 1; off >>= 1) {
        s  += __shfl_xor_sync(0xffffffffu, s, off);
        ss += __shfl_xor_sync(0xffffffffu, ss, off);
    }
    const float mean = s * (1.f / 64.f);
    const float var  = ss * (1.f / 64.f) - mean * mean;
    const float rstd = rsqrtf(var + EPS_);

    float2 o;
    o.x = (v.x - mean) * rstd * w[lane * 2 + 0] + bia[lane * 2 + 0];
    o.y = (v.y - mean) * rstd * w[lane * 2 + 1] + bia[lane * 2 + 1];
    *(float2*)p = o;
}

// ---------------------------------------------------------------------------
// Flash-style causal attention; epilogue emits bf16 hi/lo split of O.
// ---------------------------------------------------------------------------
__global__ __launch_bounds__(256) void attn_causal(const float* __restrict__ q,
                                                   const float* __restrict__ k,
                                                   const float* __restrict__ v,
                                                   __nv_bfloat16* __restrict__ oh,
                                                   __nv_bfloat16* __restrict__ ol) {
    __shared__ float Qs[64][68];
    __shared__ float Ks[32][68];
    __shared__ float Vs[32][68];
    __shared__ float Ps[64][36];

    const int tid = threadIdx.x;
    const int bh = blockIdx.y;
    const int b  = bh >> 4;
    const int h  = bh & 15;
    const int i0 = blockIdx.x * 64;

    const size_t head_off = (size_t)b * T_ * E_ + (size_t)h * 64;
    const float* qb = q + head_off;
    const float* kb = k + head_off;
    const float* vb = v + head_off;

    {
        const int r = tid >> 2;
        const int seg = (tid & 3) * 16;
        const float* src = qb + (size_t)(i0 + r) * E_ + seg;
#pragma unroll
        for (int f = 0; f < 4; f++) {
            float4 x4 = *(const float4*)(src + 4 * f);
            *(float4*)&Qs[r][seg + 4 * f] = x4;
        }
    }

    const int ty = tid >> 4;
    const int tx = tid & 15;

    float o_acc[4][4];
    float m_i[4], l_i[4];
#pragma unroll
    for (int ri = 0; ri < 4; ri++) {
        m_i[ri] = -1e30f; l_i[ri] = 0.f;
#pragma unroll
        for (int c = 0; c < 4; c++) o_acc[ri][c] = 0.f;
    }

    const float scale = 0.125f;
    const int jend = i0 + 64;

    for (int j0 = 0; j0 < jend; j0 += 32) {
        {
            const int r = tid >> 3;
            const int seg = (tid & 7) * 8;
            const float* ks = kb + (size_t)(j0 + r) * E_ + seg;
            const float* vs = vb + (size_t)(j0 + r) * E_ + seg;
            *(float4*)&Ks[r][seg + 0] = *(const float4*)(ks + 0);
            *(float4*)&Ks[r][seg + 4] = *(const float4*)(ks + 4);
            *(float4*)&Vs[r][seg + 0] = *(const float4*)(vs + 0);
            *(float4*)&Vs[r][seg + 4] = *(const float4*)(vs + 4);
        }
        __syncthreads();

        float s[4][2];
#pragma unroll
        for (int ri = 0; ri < 4; ri++) { s[ri][0] = 0.f; s[ri][1] = 0.f; }
#pragma unroll
        for (int d = 0; d < 64; d += 4) {
            float4 b0 = *(const float4*)&Ks[tx * 2 + 0][d];
            float4 b1 = *(const float4*)&Ks[tx * 2 + 1][d];
#pragma unroll
            for (int ri = 0; ri < 4; ri++) {
                float4 a = *(const float4*)&Qs[ty * 4 + ri][d];
                s[ri][0] += a.x * b0.x + a.y * b0.y + a.z * b0.z + a.w * b0.w;
                s[ri][1] += a.x * b1.x + a.y * b1.y + a.z * b1.z + a.w * b1.w;
            }
        }

#pragma unroll
        for (int ri = 0; ri < 4; ri++) {
            const int gi = i0 + ty * 4 + ri;
            const int gj0 = j0 + tx * 2;
            float s0 = (gj0 + 0 <= gi) ? s[ri][0] * scale : -1e30f;
            float s1 = (gj0 + 1 <= gi) ? s[ri][1] * scale : -1e30f;

            float mt = fmaxf(s0, s1);
#pragma unroll
            for (int off = 8; off >= 1; off >>= 1)
                mt = fmaxf(mt, __shfl_xor_sync(0xffffffffu, mt, off));

            const float mnew = fmaxf(m_i[ri], mt);
            const float corr = __expf(m_i[ri] - mnew);
            const float p0 = __expf(s0 - mnew);
            const float p1 = __expf(s1 - mnew);
            float rs = p0 + p1;
#pragma unroll
            for (int off = 8; off >= 1; off >>= 1)
                rs += __shfl_xor_sync(0xffffffffu, rs, off);

            l_i[ri] = l_i[ri] * corr + rs;
            m_i[ri] = mnew;
#pragma unroll
            for (int c = 0; c < 4; c++) o_acc[ri][c] *= corr;

            Ps[ty * 4 + ri][tx * 2 + 0] = p0;
            Ps[ty * 4 + ri][tx * 2 + 1] = p1;
        }
        __syncthreads();

#pragma unroll
        for (int j = 0; j < 32; j++) {
            float4 vv = *(const float4*)&Vs[j][tx * 4];
#pragma unroll
            for (int ri = 0; ri < 4; ri++) {
                const float pp = Ps[ty * 4 + ri][j];
                o_acc[ri][0] = fmaf(pp, vv.x, o_acc[ri][0]);
                o_acc[ri][1] = fmaf(pp, vv.y, o_acc[ri][1]);
                o_acc[ri][2] = fmaf(pp, vv.z, o_acc[ri][2]);
                o_acc[ri][3] = fmaf(pp, vv.w, o_acc[ri][3]);
            }
        }
        __syncthreads();
    }

#pragma unroll
    for (int ri = 0; ri < 4; ri++) {
        const float inv = 1.f / l_i[ri];
        __nv_bfloat16 hh[4], ll[4];
#pragma unroll
        for (int c = 0; c < 4; c++) {
            const float val = o_acc[ri][c] * inv;
            hh[c] = __float2bfloat16(val);
            ll[c] = __float2bfloat16(val - __bfloat162float(hh[c]));
        }
        const size_t idx = (size_t)(b * T_ + i0 + ty * 4 + ri) * E_ + h * 64 + tx * 4;
        *(uint2*)(oh + idx) = *(uint2*)hh;
        *(uint2*)(ol + idx) = *(uint2*)ll;
    }
}

// ---------------------------------------------------------------------------
// Launch
// ---------------------------------------------------------------------------
extern "C" void kernel_launch(void* const* d_in, const int* in_sizes, int n_in,
                              void* d_out, int out_size) {
    const float* x     = (const float*)d_in[0];
    const float* Wk    = (const float*)d_in[1];
    const float* Wq    = (const float*)d_in[2];
    const float* Wv    = (const float*)d_in[3];
    const float* Wu    = (const float*)d_in[4];
    const float* kln_w = (const float*)d_in[5];
    const float* kln_b = (const float*)d_in[6];
    const float* qln_w = (const float*)d_in[7];
    const float* qln_b = (const float*)d_in[8];
    float* out = (float*)d_out;

    float *qp, *kp, *vp;
    __nv_bfloat16 *xh, *xl, *oh, *ol, *wh, *wl;
    cudaGetSymbolAddress((void**)&qp, g_q);
    cudaGetSymbolAddress((void**)&kp, g_k);
    cudaGetSymbolAddress((void**)&vp, g_v);
    cudaGetSymbolAddress((void**)&xh, g_xh);
    cudaGetSymbolAddress((void**)&xl, g_xl);
    cudaGetSymbolAddress((void**)&oh, g_oh);
    cudaGetSymbolAddress((void**)&ol, g_ol);
    cudaGetSymbolAddress((void**)&wh, g_wh);
    cudaGetSymbolAddress((void**)&wl, g_wl);

    __nv_bfloat16* wkh = wh + 0 * (size_t)E_ * E_;
    __nv_bfloat16* wqh = wh + 1 * (size_t)E_ * E_;
    __nv_bfloat16* wvh = wh + 2 * (size_t)E_ * E_;
    __nv_bfloat16* wuh = wh + 3 * (size_t)E_ * E_;
    __nv_bfloat16* wkl = wl + 0 * (size_t)E_ * E_;
    __nv_bfloat16* wql = wl + 1 * (size_t)E_ * E_;
    __nv_bfloat16* wvl = wl + 2 * (size_t)E_ * E_;
    __nv_bfloat16* wul = wl + 3 * (size_t)E_ * E_;

    cudaFuncSetAttribute(gemm_bf16_split,
                         cudaFuncAttributeMaxDynamicSharedMemorySize,
                         SMEM_GEMM_TOTAL);

    // splits
    const int nx4 = ROWS_ * E_ / 4;
    const int nw4 = E_ * E_ / 4;
    split_bf16<<<(nx4 + 255) / 256, 256>>>(x, xh, xl, nx4);
    split_bf16<<<(nw4 + 255) / 256, 256>>>(Wk, wkh, wkl, nw4);
    split_bf16<<<(nw4 + 255) / 256, 256>>>(Wq, wqh, wql, nw4);
    split_bf16<<<(nw4 + 255) / 256, 256>>>(Wv, wvh, wvl, nw4);
    split_bf16<<<(nw4 + 255) / 256, 256>>>(Wu, wuh, wul, nw4);

    // fused QKV GEMM
    dim3 gQKV(E_ / 128, ROWS_ / 128, 3);
    gemm_bf16_split<<<gQKV, 256, SMEM_GEMM_TOTAL>>>(
        xh, xl, wkh, wkl, kp, wqh, wql, qp, wvh, wvl, vp);

    const int ln_rows = ROWS_ * H_;
    ln_head<<<ln_rows / 8, 256>>>(kp, kln_w, kln_b, ln_rows);
    ln_head<<<ln_rows / 8, 256>>>(qp, qln_w, qln_b, ln_rows);

    dim3 gAttn(T_ / 64, B_ * H_);
    attn_causal<<<gAttn, 256>>>(qp, kp, vp, oh, ol);

    dim3 gOut(E_ / 128, ROWS_ / 128, 1);
    gemm_bf16_split<<<gOut, 256, SMEM_GEMM_TOTAL>>>(
        oh, ol, wuh, wul, out, wuh, wul, out, wuh, wul, out);
}